// round 13
// baseline (speedup 1.0000x reference)
#include <cuda_runtime.h>
#include <cuda_fp16.h>
#include <cuda_bf16.h>

#define NBINS 256
#define NIMG  96
#define BATCH 48            // 2 batches: scratch 25.2 MB, safely L2-resident
#define HDIM  512
#define WDIM  512
#define CHUNK 16
#define PI_F  3.14159265358979323846f

// scratch: 4 parity copies x BATCH imgs x 128x128 tiles, cell = 4 x fp16 = 8B.
// Zero-initialized at load; merge restores owned regions to zero each call
// (block-exclusive coalesced stores) -> graph-replay safe.
#define BUF_WORDS (4 * BATCH * 128 * 128 * 2)
__device__ unsigned g_buf[BUF_WORDS];
__device__ unsigned g_vmax_u[NIMG];

__device__ __forceinline__ void red_h4(unsigned* a, unsigned u0, unsigned u1) {
    asm volatile("red.global.add.noftz.v2.f16x2 [%0], {%1,%2};"
                 :: "l"(a), "r"(u0), "r"(u1) : "memory");
}

// ---------------------------------------------------------------------------
// Kernel 1: soft co-occurrence scatter, ONE 8B fp16 red per pixel pair.
// Parity copy c = (ia&1)*2 + (ib&1); tile (tr,tc) = ((ia+1)>>1, (ib+1)>>1).
// Cell half lanes: {wa0wb0, wa0wb1 | wa1wb0, wa1wb1} (word = row-half).
// X loaded with __ldcs (streaming, evict-first) so it never displaces scratch.
// grid = (2, 32, BATCH), block = 256
// ---------------------------------------------------------------------------
__global__ void __launch_bounds__(256) k_hist(const float* __restrict__ X,
                                              int img0, int zero_vmax) {
    if (zero_vmax && blockIdx.x == 0 && blockIdx.y == 0 && blockIdx.z == 0 &&
        threadIdx.x < NIMG)
        g_vmax_u[threadIdx.x] = 0u;

    const int img_l = blockIdx.z;
    const int col   = blockIdx.x * blockDim.x + threadIdx.x;
    const int r0    = blockIdx.y * CHUNK;

    const float* __restrict__ base =
        X + (size_t)(img0 + img_l) * (HDIM * WDIM) + col;

    float a  = __ldcs(base + (size_t)r0 * WDIM);
    float fa = fminf(floorf(a), 254.0f);
    int   ia = (int)fa;
    float wa0 = 0.5f * (1.0f + __cosf(PI_F * (a - fa)));

    const int rmax = min(r0 + CHUNK, HDIM - 1);
    for (int r = r0; r < rmax; ++r) {
        float b  = __ldcs(base + (size_t)(r + 1) * WDIM);
        float fb = fminf(floorf(b), 254.0f);
        int   ib = (int)fb;
        float wb0 = 0.5f * (1.0f + __cosf(PI_F * (b - fb)));

        const float wa1 = 1.0f - wa0;
        const float wb1 = 1.0f - wb0;

        const int c  = ((ia & 1) << 1) | (ib & 1);
        const int tr = (ia + 1) >> 1;
        const int tc = (ib + 1) >> 1;
        unsigned* p = g_buf + ((((c * BATCH + img_l) << 14) + (tr << 7) + tc) << 1);

        __half2 h0 = __floats2half2_rn(wa0 * wb0, wa0 * wb1);
        __half2 h1 = __floats2half2_rn(wa1 * wb0, wa1 * wb1);
        red_h4(p, reinterpret_cast<unsigned&>(h0), reinterpret_cast<unsigned&>(h1));

        a = b; ia = ib; wa0 = wb0;
    }
}

// ---------------------------------------------------------------------------
// Kernel 2: merge + self-zero + per-image max. 256 threads, 2 bins/thread.
// Block bx -> output rows i = 2bx, 2bx+1. Thread t: di=t>>7, jp=t&127;
// bins (i, 2jp), (i, 2jp+1). All scratch reads are coalesced uint2
// full-cell loads; needed halves extracted in registers.
// Zero ownership (exclusive to block bx): copies 0,1 full cell-row bx
// (uint2); copies 2,3 word1 of row bx + word0 of row bx+1.
// grid = (128, BATCH), block = 256
// ---------------------------------------------------------------------------
__global__ void __launch_bounds__(256) k_merge(float* __restrict__ out,
                                               int img0) {
    const int img_l = blockIdx.y;
    const int bx  = blockIdx.x;
    const int t   = threadIdx.x;
    const int di  = t >> 7;
    const int jp  = t & 127;
    const int i   = (bx << 1) + di;

    const uint2* __restrict__ buf2 = reinterpret_cast<const uint2*>(g_buf);

    float s0 = 0.0f, s1 = 0.0f;
    #pragma unroll
    for (int pr = 0; pr < 2; ++pr) {
        const int tr = (i + pr) >> 1;
        const int ra = (i + pr) & 1;
        if (tr < 128) {
            const int c0 = pr << 1;
            const int c1 = c0 | 1;
            const int cb0 = ((c0 * BATCH + img_l) << 14) + (tr << 7);
            const int cb1 = ((c1 * BATCH + img_l) << 14) + (tr << 7);

            uint2 u0 = buf2[cb0 + jp];
            unsigned w = ra ? u0.y : u0.x;
            float2 v = __half22float2(reinterpret_cast<__half2&>(w));
            s0 += v.x;
            s1 += v.y;

            uint2 uA = buf2[cb1 + jp];
            unsigned wA = ra ? uA.y : uA.x;
            s0 += __high2float(reinterpret_cast<__half2&>(wA));

            if (jp < 127) {
                uint2 uB = buf2[cb1 + jp + 1];
                unsigned wB = ra ? uB.y : uB.x;
                s1 += __low2float(reinterpret_cast<__half2&>(wB));
            }
        }
    }
    reinterpret_cast<float2*>(out + ((size_t)(img0 + img_l) << 16) + (i << 8))[jp] =
        make_float2(s0, s1);

    __syncthreads();   // all block reads done before zeroing owned region

    // A) copies 0,1: full cell-row bx (uint2 store per thread)
    {
        const int pc = t >> 7;
        const int tc = t & 127;
        reinterpret_cast<uint2*>(g_buf)[((pc * BATCH + img_l) << 14) + (bx << 7) + tc] =
            make_uint2(0u, 0u);
    }
    // B) copies 2,3: word1 of row bx, word0 of row bx+1
    {
        const int c  = 2 + (t >> 7);
        const int tc = t & 127;
        const int wb = ((((c * BATCH + img_l) << 14) + (bx << 7) + tc) << 1);
        g_buf[wb + 1] = 0u;
        if (bx < 127)
            g_buf[wb + 256] = 0u;    // cell (bx+1, tc), word 0
    }

    // per-image max (values >= 0: uint bits monotonic)
    float m = fmaxf(s0, s1);
    #pragma unroll
    for (int o = 16; o > 0; o >>= 1)
        m = fmaxf(m, __shfl_xor_sync(0xFFFFFFFFu, m, o));
    __shared__ float sm[8];
    if ((t & 31) == 0) sm[t >> 5] = m;
    __syncthreads();
    if (t < 8) {
        m = sm[t];
        #pragma unroll
        for (int o = 4; o > 0; o >>= 1)
            m = fmaxf(m, __shfl_xor_sync(0xFFu, m, o));
        if (t == 0)
            atomicMax(&g_vmax_u[img0 + img_l], __float_as_uint(m));
    }
}

// ---------------------------------------------------------------------------
// Kernel 3: scale each histogram by 1/vmax.  grid = (64, NIMG)
// ---------------------------------------------------------------------------
__global__ void __launch_bounds__(256) k_norm(float* __restrict__ out) {
    const int img = blockIdx.y;
    const float inv = 1.0f / __uint_as_float(g_vmax_u[img]);
    float4* __restrict__ h4 = reinterpret_cast<float4*>(out + ((size_t)img << 16));
    const int i = blockIdx.x * blockDim.x + threadIdx.x;   // [0, 16384)
    float4 v = h4[i];
    v.x *= inv; v.y *= inv; v.z *= inv; v.w *= inv;
    h4[i] = v;
}

// ---------------------------------------------------------------------------
extern "C" void kernel_launch(void* const* d_in, const int* in_sizes, int n_in,
                              void* d_out, int out_size) {
    const float* X = (const float*)d_in[0];
    float* out = (float*)d_out;

    const dim3 hgrid(WDIM / 256, (HDIM - 1 + CHUNK - 1) / CHUNK, BATCH);
    const dim3 mgrid(128, BATCH);

    for (int b = 0; b < NIMG / BATCH; ++b) {
        k_hist <<<hgrid, 256>>>(X, b * BATCH, b == 0);
        k_merge<<<mgrid, 256>>>(out, b * BATCH);
    }

    dim3 ngrid((NBINS * NBINS / 4) / 256, NIMG);
    k_norm<<<ngrid, 256>>>(out);
}

// round 14
// speedup vs baseline: 1.0038x; 1.0038x over previous
#include <cuda_runtime.h>
#include <cuda_fp16.h>
#include <cuda_bf16.h>

#define NBINS 256
#define NIMG  96
#define BATCH 96            // single batch; X streamed with __ldcs
#define HDIM  512
#define WDIM  512
#define CHUNK 16
#define PI_F  3.14159265358979323846f

// scratch: 4 parity copies x 96 imgs x 128x128 tiles, cell = 4 x fp16 = 8B.
// Zero-initialized at load; merge restores owned regions to zero each call
// (block-exclusive coalesced stores) -> graph-replay safe.
#define BUF_WORDS (4 * BATCH * 128 * 128 * 2)
__device__ unsigned g_buf[BUF_WORDS];
__device__ unsigned g_vmax_u[NIMG];

__device__ __forceinline__ void red_h4(unsigned* a, unsigned u0, unsigned u1) {
    asm volatile("red.global.add.noftz.v2.f16x2 [%0], {%1,%2};"
                 :: "l"(a), "r"(u0), "r"(u1) : "memory");
}

// ---------------------------------------------------------------------------
// Kernel 1: soft co-occurrence scatter, ONE 8B fp16 red per pixel pair.
// Parity copy c = (ia&1)*2 + (ib&1); tile (tr,tc) = ((ia+1)>>1, (ib+1)>>1).
// Cell half lanes: {wa0wb0, wa0wb1 | wa1wb0, wa1wb1} (word = row-half).
// X loaded with __ldcs (streaming, evict-first) so it never displaces scratch.
// grid = (2, 32, 96), block = 256
// ---------------------------------------------------------------------------
__global__ void __launch_bounds__(256) k_hist(const float* __restrict__ X) {
    if (blockIdx.x == 0 && blockIdx.y == 0 && blockIdx.z == 0 &&
        threadIdx.x < NIMG)
        g_vmax_u[threadIdx.x] = 0u;

    const int img = blockIdx.z;
    const int col = blockIdx.x * blockDim.x + threadIdx.x;
    const int r0  = blockIdx.y * CHUNK;

    const float* __restrict__ base = X + (size_t)img * (HDIM * WDIM) + col;

    float a  = __ldcs(base + (size_t)r0 * WDIM);
    float fa = fminf(floorf(a), 254.0f);
    int   ia = (int)fa;
    float wa0 = 0.5f * (1.0f + __cosf(PI_F * (a - fa)));

    const int rmax = min(r0 + CHUNK, HDIM - 1);
    for (int r = r0; r < rmax; ++r) {
        float b  = __ldcs(base + (size_t)(r + 1) * WDIM);
        float fb = fminf(floorf(b), 254.0f);
        int   ib = (int)fb;
        float wb0 = 0.5f * (1.0f + __cosf(PI_F * (b - fb)));

        const float wa1 = 1.0f - wa0;
        const float wb1 = 1.0f - wb0;

        const int c  = ((ia & 1) << 1) | (ib & 1);
        const int tr = (ia + 1) >> 1;
        const int tc = (ib + 1) >> 1;
        unsigned* p = g_buf + ((((c * BATCH + img) << 14) + (tr << 7) + tc) << 1);

        __half2 h0 = __floats2half2_rn(wa0 * wb0, wa0 * wb1);
        __half2 h1 = __floats2half2_rn(wa1 * wb0, wa1 * wb1);
        red_h4(p, reinterpret_cast<unsigned&>(h0), reinterpret_cast<unsigned&>(h1));

        a = b; ia = ib; wa0 = wb0;
    }
}

// ---------------------------------------------------------------------------
// Kernel 2: merge + self-zero + per-image max. 256 threads, 2 bins/thread.
// Block bx -> output rows i = 2bx, 2bx+1. Thread t: di=t>>7, jp=t&127;
// bins (i, 2jp), (i, 2jp+1). All scratch reads are coalesced uint2
// full-cell loads; needed halves extracted in registers.
// Zero ownership (exclusive to block bx): copies 0,1 full cell-row bx
// (uint2); copies 2,3 word1 of row bx + word0 of row bx+1.
// grid = (128, 96), block = 256
// ---------------------------------------------------------------------------
__global__ void __launch_bounds__(256) k_merge(float* __restrict__ out) {
    const int img = blockIdx.y;
    const int bx  = blockIdx.x;
    const int t   = threadIdx.x;
    const int di  = t >> 7;
    const int jp  = t & 127;
    const int i   = (bx << 1) + di;

    const uint2* __restrict__ buf2 = reinterpret_cast<const uint2*>(g_buf);

    float s0 = 0.0f, s1 = 0.0f;
    #pragma unroll
    for (int pr = 0; pr < 2; ++pr) {
        const int tr = (i + pr) >> 1;
        const int ra = (i + pr) & 1;
        if (tr < 128) {
            const int c0 = pr << 1;
            const int c1 = c0 | 1;
            const int cb0 = ((c0 * BATCH + img) << 14) + (tr << 7);
            const int cb1 = ((c1 * BATCH + img) << 14) + (tr << 7);

            uint2 u0 = buf2[cb0 + jp];
            unsigned w = ra ? u0.y : u0.x;
            float2 v = __half22float2(reinterpret_cast<__half2&>(w));
            s0 += v.x;
            s1 += v.y;

            uint2 uA = buf2[cb1 + jp];
            unsigned wA = ra ? uA.y : uA.x;
            s0 += __high2float(reinterpret_cast<__half2&>(wA));

            if (jp < 127) {
                uint2 uB = buf2[cb1 + jp + 1];
                unsigned wB = ra ? uB.y : uB.x;
                s1 += __low2float(reinterpret_cast<__half2&>(wB));
            }
        }
    }
    reinterpret_cast<float2*>(out + ((size_t)img << 16) + (i << 8))[jp] =
        make_float2(s0, s1);

    __syncthreads();   // all block reads done before zeroing owned region

    // A) copies 0,1: full cell-row bx (uint2 store per thread)
    {
        const int pc = t >> 7;
        const int tc = t & 127;
        reinterpret_cast<uint2*>(g_buf)[((pc * BATCH + img) << 14) + (bx << 7) + tc] =
            make_uint2(0u, 0u);
    }
    // B) copies 2,3: word1 of row bx, word0 of row bx+1
    {
        const int c  = 2 + (t >> 7);
        const int tc = t & 127;
        const int wb = ((((c * BATCH + img) << 14) + (bx << 7) + tc) << 1);
        g_buf[wb + 1] = 0u;
        if (bx < 127)
            g_buf[wb + 256] = 0u;    // cell (bx+1, tc), word 0
    }

    // per-image max (values >= 0: uint bits monotonic)
    float m = fmaxf(s0, s1);
    #pragma unroll
    for (int o = 16; o > 0; o >>= 1)
        m = fmaxf(m, __shfl_xor_sync(0xFFFFFFFFu, m, o));
    __shared__ float sm[8];
    if ((t & 31) == 0) sm[t >> 5] = m;
    __syncthreads();
    if (t < 8) {
        m = sm[t];
        #pragma unroll
        for (int o = 4; o > 0; o >>= 1)
            m = fmaxf(m, __shfl_xor_sync(0xFFu, m, o));
        if (t == 0)
            atomicMax(&g_vmax_u[img], __float_as_uint(m));
    }
}

// ---------------------------------------------------------------------------
// Kernel 3: scale each histogram by 1/vmax.  grid = (64, NIMG)
// ---------------------------------------------------------------------------
__global__ void __launch_bounds__(256) k_norm(float* __restrict__ out) {
    const int img = blockIdx.y;
    const float inv = 1.0f / __uint_as_float(g_vmax_u[img]);
    float4* __restrict__ h4 = reinterpret_cast<float4*>(out + ((size_t)img << 16));
    const int i = blockIdx.x * blockDim.x + threadIdx.x;   // [0, 16384)
    float4 v = h4[i];
    v.x *= inv; v.y *= inv; v.z *= inv; v.w *= inv;
    h4[i] = v;
}

// ---------------------------------------------------------------------------
extern "C" void kernel_launch(void* const* d_in, const int* in_sizes, int n_in,
                              void* d_out, int out_size) {
    const float* X = (const float*)d_in[0];
    float* out = (float*)d_out;

    const dim3 hgrid(WDIM / 256, (HDIM - 1 + CHUNK - 1) / CHUNK, NIMG);
    const dim3 mgrid(128, NIMG);

    k_hist <<<hgrid, 256>>>(X);
    k_merge<<<mgrid, 256>>>(out);

    dim3 ngrid((NBINS * NBINS / 4) / 256, NIMG);
    k_norm<<<ngrid, 256>>>(out);
}

// round 15
// speedup vs baseline: 1.0306x; 1.0267x over previous
#include <cuda_runtime.h>
#include <cuda_fp16.h>
#include <cuda_bf16.h>

#define NBINS 256
#define NIMG  96
#define BATCH 48            // 2 batches: scratch 25.2 MB, proven L2-resident
#define HDIM  512
#define WDIM  512
#define CHUNK 16
#define PI_F  3.14159265358979323846f

// scratch: 4 parity copies x BATCH imgs x 128x128 tiles, cell = 4 x fp16 = 8B.
// Zero-initialized at load; merge restores owned regions to zero each call
// (block-exclusive coalesced stores) -> graph-replay safe.
#define BUF_WORDS (4 * BATCH * 128 * 128 * 2)
__device__ unsigned g_buf[BUF_WORDS];
__device__ unsigned g_vmax_u[NIMG];

__device__ __forceinline__ void red_h4(unsigned* a, unsigned u0, unsigned u1) {
    asm volatile("red.global.add.noftz.v2.f16x2 [%0], {%1,%2};"
                 :: "l"(a), "r"(u0), "r"(u1) : "memory");
}
__device__ __forceinline__ float2 h2f(unsigned w) {
    return __half22float2(reinterpret_cast<__half2&>(w));
}

// ---------------------------------------------------------------------------
// Kernel 1: soft co-occurrence scatter, ONE 8B fp16 red per pixel pair.
// Parity copy c = (ia&1)*2 + (ib&1); tile (tr,tc) = ((ia+1)>>1, (ib+1)>>1).
// Cell: word0 = row ia (lo=col ib, hi=col ib+1), word1 = row ia+1.
// grid = (2, 32, BATCH), block = 256
// ---------------------------------------------------------------------------
__global__ void __launch_bounds__(256) k_hist(const float* __restrict__ X,
                                              int img0, int zero_vmax) {
    if (zero_vmax && blockIdx.x == 0 && blockIdx.y == 0 && blockIdx.z == 0 &&
        threadIdx.x < NIMG)
        g_vmax_u[threadIdx.x] = 0u;

    const int img_l = blockIdx.z;
    const int col   = blockIdx.x * blockDim.x + threadIdx.x;
    const int r0    = blockIdx.y * CHUNK;

    const float* __restrict__ base =
        X + (size_t)(img0 + img_l) * (HDIM * WDIM) + col;

    float a  = __ldcs(base + (size_t)r0 * WDIM);
    float fa = fminf(floorf(a), 254.0f);
    int   ia = (int)fa;
    float wa0 = 0.5f * (1.0f + __cosf(PI_F * (a - fa)));

    const int rmax = min(r0 + CHUNK, HDIM - 1);
    for (int r = r0; r < rmax; ++r) {
        float b  = __ldcs(base + (size_t)(r + 1) * WDIM);
        float fb = fminf(floorf(b), 254.0f);
        int   ib = (int)fb;
        float wb0 = 0.5f * (1.0f + __cosf(PI_F * (b - fb)));

        const float wa1 = 1.0f - wa0;
        const float wb1 = 1.0f - wb0;

        const int c  = ((ia & 1) << 1) | (ib & 1);
        const int tr = (ia + 1) >> 1;
        const int tc = (ib + 1) >> 1;
        unsigned* p = g_buf + ((((c * BATCH + img_l) << 14) + (tr << 7) + tc) << 1);

        __half2 h0 = __floats2half2_rn(wa0 * wb0, wa0 * wb1);
        __half2 h1 = __floats2half2_rn(wa1 * wb0, wa1 * wb1);
        red_h4(p, reinterpret_cast<unsigned&>(h0), reinterpret_cast<unsigned&>(h1));

        a = b; ia = ib; wa0 = wb0;
    }
}

// ---------------------------------------------------------------------------
// Kernel 2: quad merge + self-zero + per-image max.
// Thread t of block (bx, img): quad-row iq = 2bx + (t>>7), col-quad jq = t&127;
// owns output bins (2iq+di, 2jq+dj), di,dj in {0,1}. 9 uint2 cell loads per
// quad. Zero ownership: copies 0,1 full cell-row iq; copies 2,3 word1 of
// row iq + word0 of row iq+1 (row 0 word0 never written by hist).
// grid = (64, BATCH), block = 256
// ---------------------------------------------------------------------------
__global__ void __launch_bounds__(256) k_merge(float* __restrict__ out,
                                               int img0) {
    const int img_l = blockIdx.y;
    const int t  = threadIdx.x;
    const int iq = (blockIdx.x << 1) + (t >> 7);
    const int jq = t & 127;

    const uint2* __restrict__ buf2 = reinterpret_cast<const uint2*>(g_buf);

#define CELL(c, r, cc) (((((c) * BATCH + img_l) << 14) + ((r) << 7) + (cc)))

    float s00 = 0.f, s01 = 0.f, s10 = 0.f, s11 = 0.f;
    uint2 u;
    float2 f;

    // copy 0, cell (iq, jq): all four bins
    u = buf2[CELL(0, iq, jq)];
    f = h2f(u.x); s00 += f.x; s01 += f.y;
    f = h2f(u.y); s10 += f.x; s11 += f.y;

    // copy 1, cell (iq, jq): hi halves -> dj=0 bins
    u = buf2[CELL(1, iq, jq)];
    s00 += h2f(u.x).y;
    s10 += h2f(u.y).y;
    // copy 1, cell (iq, jq+1): lo halves -> dj=1 bins
    if (jq < 127) {
        u = buf2[CELL(1, iq, jq + 1)];
        s01 += h2f(u.x).x;
        s11 += h2f(u.y).x;
    }

    // copy 2, cell (iq, jq): word1 -> di=0 bins
    u = buf2[CELL(2, iq, jq)];
    f = h2f(u.y); s00 += f.x; s01 += f.y;
    // copy 2, cell (iq+1, jq): word0 -> di=1 bins
    if (iq < 127) {
        u = buf2[CELL(2, iq + 1, jq)];
        f = h2f(u.x); s10 += f.x; s11 += f.y;
    }

    // copy 3: four corner cells, one half each
    u = buf2[CELL(3, iq, jq)];
    s00 += h2f(u.y).y;                       // word1 hi
    if (jq < 127) {
        u = buf2[CELL(3, iq, jq + 1)];
        s01 += h2f(u.y).x;                   // word1 lo
    }
    if (iq < 127) {
        u = buf2[CELL(3, iq + 1, jq)];
        s10 += h2f(u.x).y;                   // word0 hi
        if (jq < 127) {
            u = buf2[CELL(3, iq + 1, jq + 1)];
            s11 += h2f(u.x).x;               // word0 lo
        }
    }

    // two coalesced float2 stores (rows 2iq, 2iq+1)
    {
        float2* o2 = reinterpret_cast<float2*>(out + ((size_t)(img0 + img_l) << 16));
        o2[((iq << 1) << 7) + jq]       = make_float2(s00, s01);
        o2[(((iq << 1) + 1) << 7) + jq] = make_float2(s10, s11);
    }

    __syncthreads();   // all block reads done before zeroing owned region

    // zero: copies 0,1 full cell-row iq
    {
        uint2* b2 = reinterpret_cast<uint2*>(g_buf);
        b2[CELL(0, iq, jq)] = make_uint2(0u, 0u);
        b2[CELL(1, iq, jq)] = make_uint2(0u, 0u);
    }
    // zero: copies 2,3 word1 of row iq; word0 of row iq+1
    g_buf[(CELL(2, iq, jq) << 1) + 1] = 0u;
    g_buf[(CELL(3, iq, jq) << 1) + 1] = 0u;
    if (iq < 127) {
        g_buf[CELL(2, iq + 1, jq) << 1] = 0u;
        g_buf[CELL(3, iq + 1, jq) << 1] = 0u;
    }
#undef CELL

    // per-image max (values >= 0: uint bits monotonic)
    float m = fmaxf(fmaxf(s00, s01), fmaxf(s10, s11));
    #pragma unroll
    for (int o = 16; o > 0; o >>= 1)
        m = fmaxf(m, __shfl_xor_sync(0xFFFFFFFFu, m, o));
    __shared__ float sm[8];
    if ((t & 31) == 0) sm[t >> 5] = m;
    __syncthreads();
    if (t < 8) {
        m = sm[t];
        #pragma unroll
        for (int o = 4; o > 0; o >>= 1)
            m = fmaxf(m, __shfl_xor_sync(0xFFu, m, o));
        if (t == 0)
            atomicMax(&g_vmax_u[img0 + img_l], __float_as_uint(m));
    }
}

// ---------------------------------------------------------------------------
// Kernel 3: scale each histogram by 1/vmax.  grid = (64, NIMG)
// ---------------------------------------------------------------------------
__global__ void __launch_bounds__(256) k_norm(float* __restrict__ out) {
    const int img = blockIdx.y;
    const float inv = 1.0f / __uint_as_float(g_vmax_u[img]);
    float4* __restrict__ h4 = reinterpret_cast<float4*>(out + ((size_t)img << 16));
    const int i = blockIdx.x * blockDim.x + threadIdx.x;   // [0, 16384)
    float4 v = h4[i];
    v.x *= inv; v.y *= inv; v.z *= inv; v.w *= inv;
    h4[i] = v;
}

// ---------------------------------------------------------------------------
extern "C" void kernel_launch(void* const* d_in, const int* in_sizes, int n_in,
                              void* d_out, int out_size) {
    const float* X = (const float*)d_in[0];
    float* out = (float*)d_out;

    const dim3 hgrid(WDIM / 256, (HDIM - 1 + CHUNK - 1) / CHUNK, BATCH);
    const dim3 mgrid(64, BATCH);

    for (int b = 0; b < NIMG / BATCH; ++b) {
        k_hist <<<hgrid, 256>>>(X, b * BATCH, b == 0);
        k_merge<<<mgrid, 256>>>(out, b * BATCH);
    }

    dim3 ngrid((NBINS * NBINS / 4) / 256, NIMG);
    k_norm<<<ngrid, 256>>>(out);
}